// round 7
// baseline (speedup 1.0000x reference)
#include <cuda_runtime.h>
#include <cstdint>
#include <math.h>
#include <float.h>

#define NB 4096
#define TT 200
#define DD 64
#define H1 16
#define H2 8
#define TILE_FLOATS (TT * DD)            // 12800
#define TILE_BYTES  (TILE_FLOATS * 4)    // 51200

#define NEG_INF_F (-4294967296.0f)       // fp32 rounding of -(2^32)+1

typedef unsigned long long ull;

__device__ __forceinline__ void cp_async16(uint32_t smem_dst, const void* gsrc) {
    asm volatile("cp.async.cg.shared.global [%0], [%1], 16;\n"
                 :: "r"(smem_dst), "l"(gsrc));
}
__device__ __forceinline__ void cp_async_wait_all() {
    asm volatile("cp.async.wait_all;\n" ::: "memory");
}
__device__ __forceinline__ float fsigmoid(float x) {
    return __fdividef(1.0f, 1.0f + __expf(-x));
}
// ---- packed f32x2 helpers ----
__device__ __forceinline__ ull pack2(float x, float y) {
    ull r; asm("mov.b64 %0, {%1, %2};" : "=l"(r) : "f"(x), "f"(y)); return r;
}
__device__ __forceinline__ void unpack2(ull v, float& x, float& y) {
    asm("mov.b64 {%0, %1}, %2;" : "=f"(x), "=f"(y) : "l"(v));
}
__device__ __forceinline__ ull fma2(ull a, ull b, ull c) {
    ull d; asm("fma.rn.f32x2 %0, %1, %2, %3;" : "=l"(d) : "l"(a), "l"(b), "l"(c));
    return d;
}
__device__ __forceinline__ void lds_v2u64(uint32_t saddr, ull& a, ull& b) {
    asm volatile("ld.shared.v2.u64 {%0, %1}, [%2];"
                 : "=l"(a), "=l"(b) : "r"(saddr));
}

__global__ __launch_bounds__(256, 4)
void din_attn_kernel(const float* __restrict__ qg,
                     const float* __restrict__ kg,
                     const int*   __restrict__ lg,
                     const float* __restrict__ W1,
                     const float* __restrict__ b1,
                     const float* __restrict__ W2,
                     const float* __restrict__ b2,
                     const float* __restrict__ W3,
                     const float* __restrict__ b3,
                     const float* __restrict__ W4,
                     const float* __restrict__ b4,
                     float* __restrict__ outg)
{
    extern __shared__ float k_s[];                 // dense swizzled tile, 51200 B
    __shared__ __align__(16) float U[1024];        // M (pass1) / sc+op+o (later)
    __shared__ float q_s[DD];
    __shared__ float v_s[H1];
    __shared__ float W2_s[H1 * H2];
    __shared__ float b2_s[H2];
    __shared__ float W3_s[H2];
    __shared__ float red_s[8];
    __shared__ float b3_s;

    const int b   = blockIdx.x;
    const int tid = threadIdx.x;
    const uint32_t sb = (uint32_t)__cvta_generic_to_shared(k_s);
    const uint32_t Mb = (uint32_t)__cvta_generic_to_shared(U);

    // ---- issue ALL key-tile copies asynchronously (XOR-quad swizzle) ----
    {
        const char* g = (const char*)(kg + (size_t)b * TILE_FLOATS);
        #pragma unroll
        for (int it = 0; it < 12; it++) {
            int i = tid + it * 256;
            int t = i >> 4, c = i & 15;
            cp_async16(sb + t * 256 + ((c ^ (t & 15)) << 4), g + i * 16);
        }
        if (tid < 128) {
            int i = tid + 3072;
            int t = i >> 4, c = i & 15;
            cp_async16(sb + t * 256 + ((c ^ (t & 15)) << 4), g + i * 16);
        }
    }

    // ---- tiny parameter loads (overlap with async copies) ----
    if (tid < DD)      q_s[tid]  = qg[(size_t)b * DD + tid];
    if (tid >= 64 && tid < 64 + H1 * H2) W2_s[tid - 64] = W2[tid - 64];
    if (tid >= 192 && tid < 192 + H2)    { b2_s[tid - 192] = b2[tid - 192]; W3_s[tid - 192] = W3[tid - 192]; }
    if (tid == 255)    b3_s = b3[0];
    __syncthreads();

    // ---- M[d][h] = W1b - W1c + q_d * W1d  (into U) ----
    for (int i = tid; i < DD * H1; i += 256) {
        int d = i >> 4, h = i & 15;
        U[i] = W1[(64 + d) * H1 + h] - W1[(128 + d) * H1 + h]
             + q_s[d] * W1[(192 + d) * H1 + h];
    }
    // ---- v[h] = b1 + q @ (W1a + W1c) ----
    if (tid < H1) {
        float a0 = 0.f, a1 = 0.f;
        #pragma unroll 8
        for (int d = 0; d < DD; d += 2) {
            a0 = fmaf(q_s[d + 0], W1[(d + 0) * H1 + tid] + W1[(128 + d + 0) * H1 + tid], a0);
            a1 = fmaf(q_s[d + 1], W1[(d + 1) * H1 + tid] + W1[(128 + d + 1) * H1 + tid], a1);
        }
        v_s[tid] = b1[tid] + a0 + a1;
    }

    const int len = lg[b];

    cp_async_wait_all();
    __syncthreads();

    const float4* k4 = reinterpret_cast<const float4*>(k_s);

    // ---- pass 1: MLP scorer, ONE t per thread (tid < 200) ----
    float s = -FLT_MAX;
    if (tid < TT) {
        const int t = tid;
        const int x = t & 15;
        ull acc[8];
        #pragma unroll
        for (int j = 0; j < 8; j++) acc[j] = pack2(v_s[2 * j], v_s[2 * j + 1]);

        #pragma unroll 4
        for (int db = 0; db < 16; db++) {
            float4 ka = k4[t * 16 + (db ^ x)];
            #pragma unroll
            for (int sub = 0; sub < 4; sub++) {
                float a = (sub == 0) ? ka.x : (sub == 1) ? ka.y : (sub == 2) ? ka.z : ka.w;
                ull kp = pack2(a, a);
                uint32_t off = Mb + (db * 4 + sub) * 64;
                ull m[8];
                lds_v2u64(off +  0, m[0], m[1]);
                lds_v2u64(off + 16, m[2], m[3]);
                lds_v2u64(off + 32, m[4], m[5]);
                lds_v2u64(off + 48, m[6], m[7]);
                #pragma unroll
                for (int j = 0; j < 8; j++) acc[j] = fma2(kp, m[j], acc[j]);
            }
        }

        float h[H1];
        #pragma unroll
        for (int j = 0; j < 8; j++) unpack2(acc[j], h[2 * j], h[2 * j + 1]);
        #pragma unroll
        for (int j = 0; j < H1; j++) h[j] = fsigmoid(h[j]);

        float x2[H2];
        #pragma unroll
        for (int k = 0; k < H2; k++) {
            float a = b2_s[k];
            #pragma unroll
            for (int j = 0; j < H1; j++) a = fmaf(h[j], W2_s[j * H2 + k], a);
            x2[k] = fsigmoid(a);
        }
        float sc = b3_s;
        #pragma unroll
        for (int k = 0; k < H2; k++) sc = fmaf(x2[k], W3_s[k], sc);

        sc = (t < len) ? sc : NEG_INF_F;
        s = sc * 0.125f;   // 1/sqrt(64) after masking, as in reference
    }

    // ---- block softmax max (len==0 must give uniform attention) ----
    float val = s;
    #pragma unroll
    for (int o = 16; o; o >>= 1) val = fmaxf(val, __shfl_xor_sync(0xffffffffu, val, o));
    if ((tid & 31) == 0) red_s[tid >> 5] = val;
    __syncthreads();
    float mx = red_s[0];
    #pragma unroll
    for (int i = 1; i < 8; i++) mx = fmaxf(mx, red_s[i]);
    __syncthreads();   // M reads done; U reusable

    float* sc_s = U;           // [200]
    float* op_s = U + 256;     // [8][64]
    float* o_s  = U + 768;     // [64]

    // ---- exp + sum ----
    float p = 0.0f;
    if (tid < TT) { p = __expf(s - mx); sc_s[tid] = p; }
    #pragma unroll
    for (int o = 16; o; o >>= 1) p += __shfl_xor_sync(0xffffffffu, p, o);
    if ((tid & 31) == 0) red_s[tid >> 5] = p;
    __syncthreads();
    float denom = 0.0f;
    #pragma unroll
    for (int i = 0; i < 8; i++) denom += red_s[i];
    float inv = __fdividef(1.0f, denom);

    // ---- pass 2: weighted key sum, 128 threads = 8 t-groups x 16 d-quads ----
    if (tid < 128) {
        int g = tid >> 4, dq = tid & 15;
        int tb = g * 25;
        float4 acc = make_float4(0.f, 0.f, 0.f, 0.f);
        #pragma unroll 5
        for (int i = 0; i < 25; i++) {
            int t = tb + i;
            float w = sc_s[t];
            float4 kv = k4[t * 16 + (dq ^ (t & 15))];
            acc.x = fmaf(w, kv.x, acc.x);
            acc.y = fmaf(w, kv.y, acc.y);
            acc.z = fmaf(w, kv.z, acc.z);
            acc.w = fmaf(w, kv.w, acc.w);
        }
        *reinterpret_cast<float4*>(op_s + g * 64 + dq * 4) = acc;
    }
    __syncthreads();
    if (tid < DD) {
        float sum = 0.f;
        #pragma unroll
        for (int g = 0; g < 8; g++) sum += op_s[g * 64 + tid];
        o_s[tid] = sum * inv;
    }
    __syncthreads();

    // ---- projection partials: thread (g,d) sums dp in [g*16, g*16+16) ----
    {
        int g = tid >> 6, d = tid & 63;
        int dp0 = g * 16;
        float a0 = 0.f, a1 = 0.f;
        #pragma unroll
        for (int dp = 0; dp < 16; dp += 2) {
            a0 = fmaf(o_s[dp0 + dp],     W4[(dp0 + dp)     * DD + d], a0);
            a1 = fmaf(o_s[dp0 + dp + 1], W4[(dp0 + dp + 1) * DD + d], a1);
        }
        op_s[g * 64 + d] = a0 + a1;
    }
    __syncthreads();
    if (tid < DD)
        outg[(size_t)b * DD + tid] =
            (op_s[tid] + op_s[64 + tid]) + (op_s[128 + tid] + op_s[192 + tid]) + b4[tid];
}

extern "C" void kernel_launch(void* const* d_in, const int* in_sizes, int n_in,
                              void* d_out, int out_size)
{
    const float* q  = (const float*)d_in[0];
    const float* k  = (const float*)d_in[1];
    const int*   l  = (const int*)d_in[2];
    const float* W1 = (const float*)d_in[3];
    const float* b1 = (const float*)d_in[4];
    const float* W2 = (const float*)d_in[5];
    const float* b2 = (const float*)d_in[6];
    const float* W3 = (const float*)d_in[7];
    const float* b3 = (const float*)d_in[8];
    const float* W4 = (const float*)d_in[9];
    const float* b4 = (const float*)d_in[10];
    float* out = (float*)d_out;

    const int smem_bytes = TILE_BYTES;   // 51200 B dynamic
    cudaFuncSetAttribute(din_attn_kernel,
                         cudaFuncAttributeMaxDynamicSharedMemorySize, smem_bytes);

    din_attn_kernel<<<NB, 256, smem_bytes>>>(q, k, l, W1, b1, W2, b2,
                                             W3, b3, W4, b4, out);
}

// round 8
// speedup vs baseline: 1.1526x; 1.1526x over previous
#include <cuda_runtime.h>
#include <cstdint>
#include <math.h>
#include <float.h>

#define NB 4096
#define TT 200
#define DD 64
#define H1 16
#define H2 8
#define KP 68    // pitch in floats: 272B rows, 16B aligned, conflict-free

#define NEG_INF_F (-4294967296.0f)   // fp32 rounding of -(2^32)+1

typedef unsigned long long ull;

__device__ __forceinline__ void cp_async16(uint32_t smem_dst, const void* gsrc) {
    asm volatile("cp.async.cg.shared.global [%0], [%1], 16;\n"
                 :: "r"(smem_dst), "l"(gsrc));
}
__device__ __forceinline__ void cp_async_wait_all() {
    asm volatile("cp.async.wait_all;\n" ::: "memory");
}
__device__ __forceinline__ float fsigmoid(float x) {
    return __fdividef(1.0f, 1.0f + __expf(-x));
}
// ---- packed f32x2 helpers ----
__device__ __forceinline__ ull pack2(float x, float y) {
    ull r; asm("mov.b64 %0, {%1, %2};" : "=l"(r) : "f"(x), "f"(y)); return r;
}
__device__ __forceinline__ void unpack2(ull v, float& x, float& y) {
    asm("mov.b64 {%0, %1}, %2;" : "=f"(x), "=f"(y) : "l"(v));
}
__device__ __forceinline__ ull fma2(ull a, ull b, ull c) {
    ull d; asm("fma.rn.f32x2 %0, %1, %2, %3;" : "=l"(d) : "l"(a), "l"(b), "l"(c));
    return d;
}
__device__ __forceinline__ ull add2(ull a, ull b) {
    ull d; asm("add.rn.f32x2 %0, %1, %2;" : "=l"(d) : "l"(a), "l"(b));
    return d;
}
__device__ __forceinline__ void lds_v2u64(uint32_t saddr, ull& a, ull& b) {
    asm volatile("ld.shared.v2.u64 {%0, %1}, [%2];"
                 : "=l"(a), "=l"(b) : "r"(saddr));
}

__global__ __launch_bounds__(256, 3)
void din_attn_kernel(const float* __restrict__ qg,
                     const float* __restrict__ kg,
                     const int*   __restrict__ lg,
                     const float* __restrict__ W1,
                     const float* __restrict__ b1,
                     const float* __restrict__ W2,
                     const float* __restrict__ b2,
                     const float* __restrict__ W3,
                     const float* __restrict__ b3,
                     const float* __restrict__ W4,
                     const float* __restrict__ b4,
                     float* __restrict__ outg)
{
    extern __shared__ float k_s[];                  // [TT][KP] keys, 54400 B
    __shared__ __align__(16) float M_s[DD * H1];    // per-batch effective W1 (64x16)
    __shared__ __align__(16) float U[TT * H1];      // 12.8KB: comb (pass1) / sc+op+o
    __shared__ float q_s[DD];
    __shared__ float v_s[H1];
    __shared__ float W2_s[H1 * H2];
    __shared__ float b2_s[H2];
    __shared__ float W3_s[H2];
    __shared__ float red_s[8];
    __shared__ float b3_s;

    const int b   = blockIdx.x;
    const int tid = threadIdx.x;
    const uint32_t sb = (uint32_t)__cvta_generic_to_shared(k_s);

    // ---- issue ALL key-tile copies asynchronously ----
    {
        const char* g = (const char*)(kg + (size_t)b * TT * DD);
        #pragma unroll
        for (int it = 0; it < 12; it++) {
            int i = tid + it * 256;
            int t = i >> 4, c = i & 15;
            cp_async16(sb + t * (KP * 4) + c * 16, g + i * 16);
        }
        if (tid < 128) {
            int i = tid + 3072;
            int t = i >> 4, c = i & 15;
            cp_async16(sb + t * (KP * 4) + c * 16, g + i * 16);
        }
    }

    // ---- tiny parameter loads (overlap with async copies) ----
    if (tid < DD)      q_s[tid]  = qg[(size_t)b * DD + tid];
    if (tid >= 64 && tid < 64 + H1 * H2) W2_s[tid - 64] = W2[tid - 64];
    if (tid >= 192 && tid < 192 + H2)    { b2_s[tid - 192] = b2[tid - 192]; W3_s[tid - 192] = W3[tid - 192]; }
    if (tid == 255)    b3_s = b3[0];
    __syncthreads();

    // ---- M[d][h] = W1b - W1c + q_d * W1d ----
    for (int i = tid; i < DD * H1; i += 256) {
        int d = i >> 4, h = i & 15;
        M_s[i] = W1[(64 + d) * H1 + h] - W1[(128 + d) * H1 + h]
               + q_s[d] * W1[(192 + d) * H1 + h];
    }
    // ---- v[h] = b1 + q @ (W1a + W1c) ----
    if (tid < H1) {
        float a0 = 0.f, a1 = 0.f;
        #pragma unroll 8
        for (int d = 0; d < DD; d += 2) {
            a0 = fmaf(q_s[d + 0], W1[(d + 0) * H1 + tid] + W1[(128 + d + 0) * H1 + tid], a0);
            a1 = fmaf(q_s[d + 1], W1[(d + 1) * H1 + tid] + W1[(128 + d + 1) * H1 + tid], a1);
        }
        v_s[tid] = b1[tid] + a0 + a1;
    }

    const int len = lg[b];

    cp_async_wait_all();
    __syncthreads();

    // ---- pass 1: 2-t x half-d split; thread (half, i) does t0=i, t1=i+100
    //      over d in [32*half, 32*half+32) ----
    const int half = tid >> 7;       // 0 | 1
    const int i    = tid & 127;
    const bool act = i < 100;
    const int tmine = half ? i + 100 : i;

    ull accA[8], accB[8];            // partials for t0 (A) and t1 (B)
    if (act) {
        const int t0 = i, t1 = i + 100;
        #pragma unroll
        for (int j = 0; j < 8; j++) {
            ull v = (half == 0) ? pack2(v_s[2 * j], v_s[2 * j + 1]) : 0ULL;
            accA[j] = v; accB[j] = v;   // bias counted exactly once (half 0)
        }

        const float4* k40 = reinterpret_cast<const float4*>(k_s) + t0 * 17 + half * 8;
        const float4* k41 = reinterpret_cast<const float4*>(k_s) + t1 * 17 + half * 8;
        const uint32_t Mb = (uint32_t)__cvta_generic_to_shared(M_s) + half * 32 * 64;

        #pragma unroll 2
        for (int db = 0; db < 8; db++) {
            float4 ka = k40[db];
            float4 kb = k41[db];
            #pragma unroll
            for (int sub = 0; sub < 4; sub++) {
                float a = (sub == 0) ? ka.x : (sub == 1) ? ka.y : (sub == 2) ? ka.z : ka.w;
                float c = (sub == 0) ? kb.x : (sub == 1) ? kb.y : (sub == 2) ? kb.z : kb.w;
                ull kpa = pack2(a, a);
                ull kpb = pack2(c, c);
                uint32_t off = Mb + (db * 4 + sub) * 64;
                ull m[8];
                lds_v2u64(off +  0, m[0], m[1]);
                lds_v2u64(off + 16, m[2], m[3]);
                lds_v2u64(off + 32, m[4], m[5]);
                lds_v2u64(off + 48, m[6], m[7]);
                #pragma unroll
                for (int j = 0; j < 8; j++) accA[j] = fma2(kpa, m[j], accA[j]);
                #pragma unroll
                for (int j = 0; j < 8; j++) accB[j] = fma2(kpb, m[j], accB[j]);
            }
        }

        // hand the partial for the OTHER half's tail-t to smem
        ull* comb = reinterpret_cast<ull*>(U);
        if (half == 0) {
            #pragma unroll
            for (int j = 0; j < 8; j++) comb[(i + 100) * 8 + j] = accB[j];
        } else {
            #pragma unroll
            for (int j = 0; j < 8; j++) comb[i * 8 + j] = accA[j];
        }
    }
    __syncthreads();

    // ---- combine + tail MLP: half0 finishes t0, half1 finishes t1 ----
    float s = -FLT_MAX;
    if (act) {
        ull* comb = reinterpret_cast<ull*>(U);
        float h[H1];
        #pragma unroll
        for (int j = 0; j < 8; j++) {
            ull mine  = half ? accB[j] : accA[j];
            ull other = comb[tmine * 8 + j];
            ull tot = add2(mine, other);
            unpack2(tot, h[2 * j], h[2 * j + 1]);
        }
        #pragma unroll
        for (int j = 0; j < H1; j++) h[j] = fsigmoid(h[j]);

        float x2[H2];
        #pragma unroll
        for (int k = 0; k < H2; k++) {
            float a = b2_s[k];
            #pragma unroll
            for (int j = 0; j < H1; j++) a = fmaf(h[j], W2_s[j * H2 + k], a);
            x2[k] = fsigmoid(a);
        }
        float sc = b3_s;
        #pragma unroll
        for (int k = 0; k < H2; k++) sc = fmaf(x2[k], W3_s[k], sc);

        sc = (tmine < len) ? sc : NEG_INF_F;
        s = sc * 0.125f;   // 1/sqrt(64) after masking, as in reference
    }

    // ---- block softmax max (len==0 must give uniform attention) ----
    float val = s;
    #pragma unroll
    for (int o = 16; o; o >>= 1) val = fmaxf(val, __shfl_xor_sync(0xffffffffu, val, o));
    if ((tid & 31) == 0) red_s[tid >> 5] = val;
    __syncthreads();
    float mx = red_s[0];
    #pragma unroll
    for (int i2 = 1; i2 < 8; i2++) mx = fmaxf(mx, red_s[i2]);
    __syncthreads();   // comb reads done; U reusable

    float* sc_s = U;           // [200]
    float* op_s = U + 256;     // [8][64]
    float* o_s  = U + 768;     // [64]

    // ---- exp + sum ----
    float p = 0.0f;
    if (act) { p = __expf(s - mx); sc_s[tmine] = p; }
    #pragma unroll
    for (int o = 16; o; o >>= 1) p += __shfl_xor_sync(0xffffffffu, p, o);
    if ((tid & 31) == 0) red_s[tid >> 5] = p;
    __syncthreads();
    float denom = 0.0f;
    #pragma unroll
    for (int i2 = 0; i2 < 8; i2++) denom += red_s[i2];
    float inv = __fdividef(1.0f, denom);

    // ---- pass 2: weighted key sum, 128 threads = 8 t-groups x 16 d-quads ----
    if (tid < 128) {
        int g = tid >> 4, dq = (tid & 15) * 4;
        int tb = g * 25;
        float4 acc = make_float4(0.f, 0.f, 0.f, 0.f);
        #pragma unroll 5
        for (int it = 0; it < 25; it++) {
            int t = tb + it;
            float w = sc_s[t];
            float4 kv = *reinterpret_cast<const float4*>(k_s + t * KP + dq);
            acc.x = fmaf(w, kv.x, acc.x);
            acc.y = fmaf(w, kv.y, acc.y);
            acc.z = fmaf(w, kv.z, acc.z);
            acc.w = fmaf(w, kv.w, acc.w);
        }
        *reinterpret_cast<float4*>(op_s + g * 64 + dq) = acc;
    }
    __syncthreads();
    if (tid < DD) {
        float sum = 0.f;
        #pragma unroll
        for (int g = 0; g < 8; g++) sum += op_s[g * 64 + tid];
        o_s[tid] = sum * inv;
    }
    __syncthreads();

    // ---- projection partials: thread (g,d) sums dp in [g*16, g*16+16) ----
    {
        int g = tid >> 6, d = tid & 63;
        int dp0 = g * 16;
        float a0 = 0.f, a1 = 0.f;
        #pragma unroll
        for (int dp = 0; dp < 16; dp += 2) {
            a0 = fmaf(o_s[dp0 + dp],     W4[(dp0 + dp)     * DD + d], a0);
            a1 = fmaf(o_s[dp0 + dp + 1], W4[(dp0 + dp + 1) * DD + d], a1);
        }
        op_s[g * 64 + d] = a0 + a1;
    }
    __syncthreads();
    if (tid < DD)
        outg[(size_t)b * DD + tid] =
            (op_s[tid] + op_s[64 + tid]) + (op_s[128 + tid] + op_s[192 + tid]) + b4[tid];
}

extern "C" void kernel_launch(void* const* d_in, const int* in_sizes, int n_in,
                              void* d_out, int out_size)
{
    const float* q  = (const float*)d_in[0];
    const float* k  = (const float*)d_in[1];
    const int*   l  = (const int*)d_in[2];
    const float* W1 = (const float*)d_in[3];
    const float* b1 = (const float*)d_in[4];
    const float* W2 = (const float*)d_in[5];
    const float* b2 = (const float*)d_in[6];
    const float* W3 = (const float*)d_in[7];
    const float* b3 = (const float*)d_in[8];
    const float* W4 = (const float*)d_in[9];
    const float* b4 = (const float*)d_in[10];
    float* out = (float*)d_out;

    const int smem_bytes = TT * KP * sizeof(float);   // 54400 B dynamic
    cudaFuncSetAttribute(din_attn_kernel,
                         cudaFuncAttributeMaxDynamicSharedMemorySize, smem_bytes);

    din_attn_kernel<<<NB, 256, smem_bytes>>>(q, k, l, W1, b1, W2, b2,
                                             W3, b3, W4, b4, out);
}